// round 10
// baseline (speedup 1.0000x reference)
#include <cuda_runtime.h>

// entmax-1.5 attention, B=8 H=8 S=1024 D=64, fp32.
// Prepass converts Q,K -> bf16 hi/lo planes and V -> transposed Vt[d][k] planes
// in device-global scratch. Main kernel: both GEMMs on mma.sync.m16n8k16
// (3-term hi/lo split), fragments via ldmatrix; entmax via Newton.

#define SEQ  1024
#define DH   64
#define QT   32
#define NTHR 512
#define PS   1036     // S/P row stride (u32 words)
#define OSS  66
#define NEWTON 10

typedef unsigned int u32;

// smem word offsets
#define S_W    0
#define KH_W   33152            // K hi plane: 256 rows x 36 w   (Vt hi: 64 x 132 w)
#define KL_W   42368            // K lo plane                    (Vt lo)
#define QH_W   51584            // Q hi plane: 32 x 36 w (Osm overlay)
#define QL_W   52736
#define TOT_W  53888
#define SMEM_BYTES (TOT_W * 4)  // 215552

// device scratch: 4,194,304 bf16 = 524288 uint4 per plane
__device__ uint4 g_QH[524288], g_QL[524288];
__device__ uint4 g_KH[524288], g_KL[524288];
__device__ uint4 g_VTH[524288], g_VTL[524288];

__device__ __forceinline__ u32 prmt(u32 a, u32 b, u32 s) {
    u32 d; asm("prmt.b32 %0, %1, %2, %3;" : "=r"(d) : "r"(a), "r"(b), "r"(s)); return d;
}
__device__ __forceinline__ u32 cvt2(float hi, float lo) {   // {bf16(hi)|bf16(lo)}
    u32 d; asm("cvt.rn.bf16x2.f32 %0, %1, %2;" : "=r"(d) : "f"(hi), "f"(lo)); return d;
}
__device__ __forceinline__ u32 pack1(float x) {             // {lo16 | hi-bf16}
    u32 Hp = cvt2(x, x);
    float h = __uint_as_float(Hp << 16);
    u32 Lp = cvt2(0.f, x - h);
    return prmt(Hp, Lp, 0x5410);
}
__device__ __forceinline__ void mma16816(float* c, const u32* a, u32 b0, u32 b1) {
    asm volatile("mma.sync.aligned.m16n8k16.row.col.f32.bf16.bf16.f32 "
        "{%0,%1,%2,%3}, {%4,%5,%6,%7}, {%8,%9}, {%0,%1,%2,%3};"
        : "+f"(c[0]), "+f"(c[1]), "+f"(c[2]), "+f"(c[3])
        : "r"(a[0]), "r"(a[1]), "r"(a[2]), "r"(a[3]), "r"(b0), "r"(b1));
}
__device__ __forceinline__ void ldmx4(u32 addr, u32* r) {
    asm volatile("ldmatrix.sync.aligned.m8n8.x4.shared.b16 {%0,%1,%2,%3}, [%4];"
        : "=r"(r[0]), "=r"(r[1]), "=r"(r[2]), "=r"(r[3]) : "r"(addr));
}
__device__ __forceinline__ void ldmx2(u32 addr, u32* r) {
    asm volatile("ldmatrix.sync.aligned.m8n8.x2.shared.b16 {%0,%1}, [%2];"
        : "=r"(r[0]), "=r"(r[1]) : "r"(addr));
}
// A frag hi+lo from packed P; p = &Sw[row0*PS + kw]
__device__ __forceinline__ void ldA(const u32* p, u32* ah, u32* al) {
    uint2 w;
    w = *(const uint2*)(p);
    ah[0] = prmt(w.x, w.y, 0x5410); al[0] = prmt(w.x, w.y, 0x7632);
    w = *(const uint2*)(p + 8 * PS);
    ah[1] = prmt(w.x, w.y, 0x5410); al[1] = prmt(w.x, w.y, 0x7632);
    w = *(const uint2*)(p + 8);
    ah[2] = prmt(w.x, w.y, 0x5410); al[2] = prmt(w.x, w.y, 0x7632);
    w = *(const uint2*)(p + 8 * PS + 8);
    al[3] = prmt(w.x, w.y, 0x7632); ah[3] = prmt(w.x, w.y, 0x5410);
}
__device__ __forceinline__ u32 s2u(const void* p) {
    u32 a;
    asm("{ .reg .u64 t; cvta.to.shared.u64 t, %1; cvt.u32.u64 %0, t; }" : "=r"(a) : "l"(p));
    return a;
}

// ===================== prepass: Q,K -> hi/lo planes ========================
__global__ void __launch_bounds__(512) prepQK(const float4* __restrict__ q,
                                              const float4* __restrict__ k)
{
    int i = blockIdx.x * 512 + threadIdx.x;   // 0..1048575
    float4 f = q[i];
    u32 h0 = cvt2(f.y, f.x), h1 = cvt2(f.w, f.z);
    u32 l0 = cvt2(f.y - __uint_as_float(h0 & 0xffff0000u),
                  f.x - __uint_as_float(h0 << 16));
    u32 l1 = cvt2(f.w - __uint_as_float(h1 & 0xffff0000u),
                  f.z - __uint_as_float(h1 << 16));
    ((uint2*)g_QH)[i] = make_uint2(h0, h1);
    ((uint2*)g_QL)[i] = make_uint2(l0, l1);
    f = k[i];
    h0 = cvt2(f.y, f.x); h1 = cvt2(f.w, f.z);
    l0 = cvt2(f.y - __uint_as_float(h0 & 0xffff0000u),
              f.x - __uint_as_float(h0 << 16));
    l1 = cvt2(f.w - __uint_as_float(h1 & 0xffff0000u),
              f.z - __uint_as_float(h1 << 16));
    ((uint2*)g_KH)[i] = make_uint2(h0, h1);
    ((uint2*)g_KL)[i] = make_uint2(l0, l1);
}

// ===================== prepass: V -> transposed hi/lo planes ===============
__global__ void __launch_bounds__(256) prepV(const float* __restrict__ v)
{
    int bh = blockIdx.x, kb = blockIdx.y;
    int d = threadIdx.x & 63, kg = threadIdx.x >> 6;
    const float* Vb = v + bh * 65536;
#pragma unroll
    for (int c = 0; c < 4; c++) {
        int k0 = kb * 128 + c * 32 + kg * 8;
        float x[8];
#pragma unroll
        for (int j = 0; j < 8; j++) x[j] = Vb[(k0 + j) * 64 + d];
        u32 h[4], l[4];
#pragma unroll
        for (int p = 0; p < 4; p++) {
            h[p] = cvt2(x[2*p+1], x[2*p]);
            l[p] = cvt2(x[2*p+1] - __uint_as_float(h[p] & 0xffff0000u),
                        x[2*p]   - __uint_as_float(h[p] << 16));
        }
        int base = (bh * 65536 + d * 1024 + k0) >> 3;
        g_VTH[base] = make_uint4(h[0], h[1], h[2], h[3]);
        g_VTL[base] = make_uint4(l[0], l[1], l[2], l[3]);
    }
}

// =========================== main kernel ===================================
__global__ void __launch_bounds__(NTHR, 1)
attn_entmax15_mma2(const float* __restrict__ qg, float* __restrict__ og)
{
    extern __shared__ u32 sm[];
    float* Sf = (float*)sm;
    u32*   Sw = sm;

    const int tid  = threadIdx.x;
    const int lane = tid & 31;
    const int wid  = tid >> 5;
    const int g    = lane >> 2;
    const int t    = lane & 3;
    const int qt   = blockIdx.x;
    const int bh   = blockIdx.y;

    float* Og = og + (size_t)bh * SEQ * DH + (size_t)qt * QT * DH;

    const u32 smb = s2u(sm);
    const u32 KHB = smb + KH_W * 4, KLB = smb + KL_W * 4;
    const u32 QHB = smb + QH_W * 4, QLB = smb + QL_W * 4;

    // ---- stage Q planes: 256 uint4 per plane ----
    {
        int pl = tid >> 8, idx = tid & 255;
        int row = idx >> 3, seg = idx & 7;
        uint4 w = (pl ? g_QL : g_QH)[(bh * 65536 + qt * 2048 + row * 64 + seg * 8) >> 3];
        *(uint4*)&sm[(pl ? QL_W : QH_W) + row * 36 + seg * 4] = w;
    }

    // ======================= GEMM1: S = Q K^T ===============================
    const int aR0   = (lane & 15) * 144;
    const int aCsel = (lane >> 4) * 16;
    const int bR    = (wid * 16 + (lane & 7)) * 144;
    const int bCsel = ((lane >> 3) & 1) * 16;

    for (int kt2 = 0; kt2 < 4; kt2++) {
        __syncthreads();
#pragma unroll
        for (int i = 0; i < 4; i++) {
            int idx = i * 512 + tid;
            int row = idx >> 3, seg = idx & 7;
            int srci = (bh * 65536 + (kt2 * 256 + row) * 64 + seg * 8) >> 3;
            *(uint4*)&sm[KH_W + row * 36 + seg * 4] = g_KH[srci];
            *(uint4*)&sm[KL_W + row * 36 + seg * 4] = g_KL[srci];
        }
        __syncthreads();

        float c[2][2][4];
#pragma unroll
        for (int m = 0; m < 2; m++)
#pragma unroll
            for (int n = 0; n < 2; n++)
#pragma unroll
                for (int r = 0; r < 4; r++) c[m][n][r] = 0.f;

#pragma unroll
        for (int ks = 0; ks < 4; ks++) {
            const int ac = ks * 32 + aCsel;
            u32 ah0[4], ah1[4], al0[4], al1[4];
            ldmx4(QHB + aR0 + ac, ah0);
            ldmx4(QHB + aR0 + 2304 + ac, ah1);
            ldmx4(QLB + aR0 + ac, al0);
            ldmx4(QLB + aR0 + 2304 + ac, al1);
            const int bc = ks * 32 + bCsel;
#pragma unroll
            for (int n = 0; n < 2; n++) {
                u32 b2h[2], b2l[2];
                ldmx2(KHB + bR + n * 1152 + bc, b2h);
                ldmx2(KLB + bR + n * 1152 + bc, b2l);
                mma16816(c[0][n], ah0, b2h[0], b2h[1]);
                mma16816(c[0][n], ah0, b2l[0], b2l[1]);
                mma16816(c[0][n], al0, b2h[0], b2h[1]);
                mma16816(c[1][n], ah1, b2h[0], b2h[1]);
                mma16816(c[1][n], ah1, b2l[0], b2l[1]);
                mma16816(c[1][n], al1, b2h[0], b2h[1]);
            }
        }
#pragma unroll
        for (int m = 0; m < 2; m++)
#pragma unroll
            for (int n = 0; n < 2; n++) {
                int row = m * 16 + g;
                int col = kt2 * 256 + wid * 16 + n * 8 + 2 * t;
                *(float2*)&Sf[row * PS + col]       = make_float2(c[m][n][0], c[m][n][1]);
                *(float2*)&Sf[(row + 8) * PS + col] = make_float2(c[m][n][2], c[m][n][3]);
            }
    }
    __syncthreads();

    // ---- zero Osm (overlays Q planes; Q dead) ----
    float* Osm = (float*)&sm[QH_W];
#pragma unroll
    for (int i = 0; i < 5; i++) {
        int idx = i * NTHR + tid;
        if (idx < QT * OSS) Osm[idx] = 0.f;
    }

    // ======================= entmax-1.5 (Newton) ============================
    for (int rr = 0; rr < 2; rr++) {
        const int row = wid * 2 + rr;
        float x[32];
        float m = -1e30f;
#pragma unroll
        for (int j = 0; j < 32; j++) {
            x[j] = Sf[row * PS + j * 32 + lane] * 0.0625f;
            m = fmaxf(m, x[j]);
        }
#pragma unroll
        for (int o = 16; o; o >>= 1) m = fmaxf(m, __shfl_xor_sync(0xffffffffu, m, o));
#pragma unroll
        for (int j = 0; j < 32; j++) x[j] -= m;

        float tau = -1.0f;
#pragma unroll 1
        for (int it = 0; it < NEWTON; it++) {
            float s = 0.f, r = 0.f;
#pragma unroll
            for (int j = 0; j < 32; j++) {
                float u = fmaxf(x[j] - tau, 0.f);
                s = fmaf(u, u, s);
                r += u;
            }
#pragma unroll
            for (int o = 16; o; o >>= 1) {
                s += __shfl_xor_sync(0xffffffffu, s, o);
                r += __shfl_xor_sync(0xffffffffu, r, o);
            }
            tau += (s - 1.0f) / (2.0f * r);
        }
#pragma unroll
        for (int j = 0; j < 32; j++) {
            float u = fmaxf(x[j] - tau, 0.f);
            Sw[row * PS + j * 32 + lane] = pack1(u * u);
        }
    }

    // ======================= GEMM2: O = P V =================================
    const int ngd = wid >> 3;      // d half
    const int khs = wid & 7;       // k slice
    const int vR    = (lane & 7) * 528;
    const int vCsel = ((lane >> 3) & 1) * 16;

    float oc[2][4][4];
#pragma unroll
    for (int m = 0; m < 2; m++)
#pragma unroll
        for (int nf = 0; nf < 4; nf++)
#pragma unroll
            for (int r = 0; r < 4; r++) oc[m][nf][r] = 0.f;

    for (int vt = 0; vt < 4; vt++) {
        __syncthreads();
#pragma unroll
        for (int i = 0; i < 4; i++) {
            int idx = i * 512 + tid;
            int row = idx >> 5, seg = idx & 31;
            int srci = (bh * 65536 + row * 1024 + vt * 256 + seg * 8) >> 3;
            *(uint4*)&sm[KH_W + row * 132 + seg * 4] = g_VTH[srci];
            *(uint4*)&sm[KL_W + row * 132 + seg * 4] = g_VTL[srci];
        }
        __syncthreads();

#pragma unroll
        for (int s2 = 0; s2 < 2; s2++) {
            const int ksl = khs * 2 + s2;
            const int kw  = vt * 256 + ksl * 16 + 2 * t;
            u32 ah[2][4], al[2][4];
            ldA(Sw + g * PS + kw, ah[0], al[0]);
            ldA(Sw + (16 + g) * PS + kw, ah[1], al[1]);
            const int vc = ksl * 32 + vCsel;
#pragma unroll
            for (int nf = 0; nf < 4; nf++) {
                const int dby = (ngd * 32 + nf * 8) * 528;
                u32 b2h[2], b2l[2];
                ldmx2(KHB + dby + vR + vc, b2h);
                ldmx2(KLB + dby + vR + vc, b2l);
#pragma unroll
                for (int m = 0; m < 2; m++) {
                    mma16816(oc[m][nf], ah[m], b2h[0], b2h[1]);
                    mma16816(oc[m][nf], ah[m], b2l[0], b2l[1]);
                    mma16816(oc[m][nf], al[m], b2h[0], b2h[1]);
                }
            }
        }
    }

    // ---- reduce k-slices into Osm ----
#pragma unroll
    for (int m = 0; m < 2; m++)
#pragma unroll
        for (int nf = 0; nf < 4; nf++) {
            int row = m * 16 + g;
            int d = ngd * 32 + nf * 8 + 2 * t;
            atomicAdd(&Osm[row * OSS + d],           oc[m][nf][0]);
            atomicAdd(&Osm[row * OSS + d + 1],       oc[m][nf][1]);
            atomicAdd(&Osm[(row + 8) * OSS + d],     oc[m][nf][2]);
            atomicAdd(&Osm[(row + 8) * OSS + d + 1], oc[m][nf][3]);
        }
    __syncthreads();

#pragma unroll
    for (int i = 0; i < (QT * DH) / NTHR; i++) {
        int idx = i * NTHR + tid;
        int q = idx >> 6, d = idx & 63;
        Og[idx] = Osm[q * OSS + d];
    }
}

extern "C" void kernel_launch(void* const* d_in, const int* in_sizes, int n_in,
                              void* d_out, int out_size)
{
    const float* q = (const float*)d_in[0];
    const float* k = (const float*)d_in[1];
    const float* v = (const float*)d_in[2];
    float* out = (float*)d_out;

    cudaFuncSetAttribute(attn_entmax15_mma2,
                         cudaFuncAttributeMaxDynamicSharedMemorySize, SMEM_BYTES);

    prepQK<<<2048, 512>>>((const float4*)q, (const float4*)k);
    prepV<<<dim3(64, 8), 256>>>(v);
    dim3 grid(SEQ / QT, 8 * 8);
    attn_entmax15_mma2<<<grid, NTHR, SMEM_BYTES>>>(q, out);
}

// round 11
// speedup vs baseline: 1.0213x; 1.0213x over previous
#include <cuda_runtime.h>

// entmax-1.5 attention, B=8 H=8 S=1024 D=64, fp32.
// Prepass: Q,K -> bf16 hi/lo planes; V -> transposed Vt[d][k] hi/lo planes.
// Main: QT=16, 256 thr, 2 CTAs/SM, cp.async double-buffered tiles,
// mma.sync.m16n8k16 with 3-term hi/lo split, Newton entmax.

#define SEQ  1024
#define DH   64
#define QT   16
#define NTHR 256
#define PS   1036        // S row stride (u32 words)
#define NEWTON 10

typedef unsigned int u32;

// smem word offsets
#define S_W   0
#define KB_W  16576      // 2 buffers x (2 planes x 64 rows x 36 w) = 9216 w
#define QP_W  25792      // 2 planes x 16 rows x 36 w = 1152 w
#define TOT_W 26944
#define SMEM_BYTES (TOT_W * 4)   // 107776

// device scratch: bf16 planes, 8MB each
__device__ uint4 g_QH[524288], g_QL[524288];
__device__ uint4 g_KH[524288], g_KL[524288];
__device__ uint4 g_VTH[524288], g_VTL[524288];

__device__ __forceinline__ u32 prmt(u32 a, u32 b, u32 s) {
    u32 d; asm("prmt.b32 %0, %1, %2, %3;" : "=r"(d) : "r"(a), "r"(b), "r"(s)); return d;
}
__device__ __forceinline__ u32 cvt2(float hi, float lo) {
    u32 d; asm("cvt.rn.bf16x2.f32 %0, %1, %2;" : "=r"(d) : "f"(hi), "f"(lo)); return d;
}
__device__ __forceinline__ u32 pack1(float x) {             // {lo16 | hi-bf16}
    u32 Hp = cvt2(x, x);
    float h = __uint_as_float(Hp << 16);
    u32 Lp = cvt2(0.f, x - h);
    return prmt(Hp, Lp, 0x5410);
}
__device__ __forceinline__ void mma16816(float* c, const u32* a, u32 b0, u32 b1) {
    asm volatile("mma.sync.aligned.m16n8k16.row.col.f32.bf16.bf16.f32 "
        "{%0,%1,%2,%3}, {%4,%5,%6,%7}, {%8,%9}, {%0,%1,%2,%3};"
        : "+f"(c[0]), "+f"(c[1]), "+f"(c[2]), "+f"(c[3])
        : "r"(a[0]), "r"(a[1]), "r"(a[2]), "r"(a[3]), "r"(b0), "r"(b1));
}
__device__ __forceinline__ void ldmx4(u32 addr, u32* r) {
    asm volatile("ldmatrix.sync.aligned.m8n8.x4.shared.b16 {%0,%1,%2,%3}, [%4];"
        : "=r"(r[0]), "=r"(r[1]), "=r"(r[2]), "=r"(r[3]) : "r"(addr));
}
__device__ __forceinline__ void ldmx2(u32 addr, u32* r) {
    asm volatile("ldmatrix.sync.aligned.m8n8.x2.shared.b16 {%0,%1}, [%2];"
        : "=r"(r[0]), "=r"(r[1]) : "r"(addr));
}
// A frag (16 rows g/g+8) hi+lo from packed P
__device__ __forceinline__ void ldA(const u32* p, u32* ah, u32* al) {
    uint2 w;
    w = *(const uint2*)(p);
    ah[0] = prmt(w.x, w.y, 0x5410); al[0] = prmt(w.x, w.y, 0x7632);
    w = *(const uint2*)(p + 8 * PS);
    ah[1] = prmt(w.x, w.y, 0x5410); al[1] = prmt(w.x, w.y, 0x7632);
    w = *(const uint2*)(p + 8);
    ah[2] = prmt(w.x, w.y, 0x5410); al[2] = prmt(w.x, w.y, 0x7632);
    w = *(const uint2*)(p + 8 * PS + 8);
    ah[3] = prmt(w.x, w.y, 0x5410); al[3] = prmt(w.x, w.y, 0x7632);
}
__device__ __forceinline__ u32 s2u(const void* p) {
    u32 a;
    asm("{ .reg .u64 t; cvta.to.shared.u64 t, %1; cvt.u32.u64 %0, t; }" : "=r"(a) : "l"(p));
    return a;
}
__device__ __forceinline__ void cp16(u32 dst, const void* src) {
    asm volatile("cp.async.ca.shared.global [%0], [%1], 16;"
                 :: "r"(dst), "l"(__cvta_generic_to_global(src)));
}
#define CP_COMMIT() asm volatile("cp.async.commit_group;" ::: "memory")
#define CP_WAIT0()  asm volatile("cp.async.wait_group 0;" ::: "memory")

// ===================== prepass: Q,K -> hi/lo planes ========================
__global__ void __launch_bounds__(512) prepQK(const float4* __restrict__ q,
                                              const float4* __restrict__ k)
{
    int i = blockIdx.x * 512 + threadIdx.x;
    float4 f = q[i];
    u32 h0 = cvt2(f.y, f.x), h1 = cvt2(f.w, f.z);
    u32 l0 = cvt2(f.y - __uint_as_float(h0 & 0xffff0000u),
                  f.x - __uint_as_float(h0 << 16));
    u32 l1 = cvt2(f.w - __uint_as_float(h1 & 0xffff0000u),
                  f.z - __uint_as_float(h1 << 16));
    ((uint2*)g_QH)[i] = make_uint2(h0, h1);
    ((uint2*)g_QL)[i] = make_uint2(l0, l1);
    f = k[i];
    h0 = cvt2(f.y, f.x); h1 = cvt2(f.w, f.z);
    l0 = cvt2(f.y - __uint_as_float(h0 & 0xffff0000u),
              f.x - __uint_as_float(h0 << 16));
    l1 = cvt2(f.w - __uint_as_float(h1 & 0xffff0000u),
              f.z - __uint_as_float(h1 << 16));
    ((uint2*)g_KH)[i] = make_uint2(h0, h1);
    ((uint2*)g_KL)[i] = make_uint2(l0, l1);
}

// ===================== prepass: V -> transposed hi/lo planes ===============
__global__ void __launch_bounds__(256) prepV(const float* __restrict__ v)
{
    int bh = blockIdx.x, kb = blockIdx.y;
    int d = threadIdx.x & 63, kg = threadIdx.x >> 6;
    const float* Vb = v + bh * 65536;
#pragma unroll
    for (int c = 0; c < 4; c++) {
        int k0 = kb * 128 + c * 32 + kg * 8;
        float x[8];
#pragma unroll
        for (int j = 0; j < 8; j++) x[j] = Vb[(k0 + j) * 64 + d];
        u32 h[4], l[4];
#pragma unroll
        for (int p = 0; p < 4; p++) {
            h[p] = cvt2(x[2*p+1], x[2*p]);
            l[p] = cvt2(x[2*p+1] - __uint_as_float(h[p] & 0xffff0000u),
                        x[2*p]   - __uint_as_float(h[p] << 16));
        }
        int base = (bh * 65536 + d * 1024 + k0) >> 3;
        g_VTH[base] = make_uint4(h[0], h[1], h[2], h[3]);
        g_VTL[base] = make_uint4(l[0], l[1], l[2], l[3]);
    }
}

// =========================== main kernel ===================================
__global__ void __launch_bounds__(NTHR, 2)
attn_entmax15_p(float* __restrict__ og)
{
    extern __shared__ u32 sm[];
    float* Sf = (float*)sm;
    u32*   Sw = sm;

    const int tid  = threadIdx.x;
    const int lane = tid & 31;
    const int wid  = tid >> 5;        // 0..7
    const int g    = lane >> 2;
    const int t    = lane & 3;
    const int qt   = blockIdx.x;      // 0..63
    const int bh   = blockIdx.y;      // 0..63

    float* Og = og + (size_t)bh * SEQ * DH + (size_t)qt * QT * DH;

    const u32 smb = s2u(sm);

    // ---- async stage Q planes (1 cp16 per thread) + K tile 0 ----
    {
        int pl = tid >> 7, rem = tid & 127, row = rem >> 3, seg = rem & 7;
        const uint4* src = (pl ? g_QL : g_QH) + bh * 8192 + (qt * 16 + row) * 8 + seg;
        cp16(smb + (QP_W + pl * 576 + row * 36 + seg * 4) * 4, src);
    }
#pragma unroll
    for (int i = 0; i < 2; i++) {     // K tile 0: 1024 chunks / 256 thr, planes split
        int idx = i * NTHR + tid;     // 0..511 : plane = idx>>8? No: 64 rows x 8 seg = 512 per plane
        int row = idx >> 3, seg = idx & 7;
        cp16(smb + (KB_W + 0 * 4608 + 0 * 2304 + row * 36 + seg * 4) * 4,
             g_KH + bh * 8192 + row * 8 + seg);
        cp16(smb + (KB_W + 0 * 4608 + 1 * 2304 + row * 36 + seg * 4) * 4,
             g_KL + bh * 8192 + row * 8 + seg);
    }
    CP_COMMIT();
    CP_WAIT0();
    __syncthreads();

    // ---- hoist Q fragments (all 4 ksteps, hi+lo) ----
    const u32 QHB = smb + QP_W * 4;
    const u32 QLB = QHB + 2304;
    const int aAdr = (lane & 15) * 144 + (lane >> 4) * 16;
    u32 qh[4][4], ql[4][4];
#pragma unroll
    for (int ks = 0; ks < 4; ks++) {
        ldmx4(QHB + aAdr + ks * 32, qh[ks]);
        ldmx4(QLB + aAdr + ks * 32, ql[ks]);
    }

    // ======================= GEMM1: S = Q K^T (16 tiles of 64 keys) ========
    const int bAdr = (wid * 8 + (lane & 7)) * 144 + ((lane >> 3) & 1) * 16;
    for (int kt = 0; kt < 16; kt++) {
        const int buf = kt & 1;
        if (kt) { CP_WAIT0(); __syncthreads(); }
        if (kt < 15) {                 // prefetch kt+1 into other buffer
            const int nb = buf ^ 1;
#pragma unroll
            for (int i = 0; i < 2; i++) {
                int idx = i * NTHR + tid;
                int row = idx >> 3, seg = idx & 7;
                int gi = bh * 8192 + ((kt + 1) * 64 + row) * 8 + seg;
                cp16(smb + (KB_W + nb * 4608 + row * 36 + seg * 4) * 4, g_KH + gi);
                cp16(smb + (KB_W + nb * 4608 + 2304 + row * 36 + seg * 4) * 4, g_KL + gi);
            }
            CP_COMMIT();
        }
        const u32 KHB = smb + (KB_W + buf * 4608) * 4;
        const u32 KLB = KHB + 9216;

        float c[4] = {0.f, 0.f, 0.f, 0.f};
#pragma unroll
        for (int ks = 0; ks < 4; ks++) {
            u32 b2h[2], b2l[2];
            ldmx2(KHB + bAdr + ks * 32, b2h);
            ldmx2(KLB + bAdr + ks * 32, b2l);
            mma16816(c, qh[ks], b2h[0], b2h[1]);
            mma16816(c, qh[ks], b2l[0], b2l[1]);
            mma16816(c, ql[ks], b2h[0], b2h[1]);
        }
        const int col = kt * 64 + wid * 8 + 2 * t;
        *(float2*)&Sf[g * PS + col]       = make_float2(c[0], c[1]);
        *(float2*)&Sf[(g + 8) * PS + col] = make_float2(c[2], c[3]);
    }
    __syncthreads();

    // ---- prefetch V tile 0 (hidden under entmax) ----
#pragma unroll
    for (int i = 0; i < 2; i++) {
        int idx = i * NTHR + tid;
        int row = idx >> 3, seg = idx & 7;     // row = d
        int gi = bh * 8192 + row * 128 + seg;  // vt = 0
        cp16(smb + (KB_W + row * 36 + seg * 4) * 4, g_VTH + gi);
        cp16(smb + (KB_W + 2304 + row * 36 + seg * 4) * 4, g_VTL + gi);
    }
    CP_COMMIT();

    // ======================= entmax-1.5 (Newton) ============================
    {
        const int row0 = wid * 2;
        for (int rr = 0; rr < 2; rr++) {
            const int row = row0 + rr;
            float x[32];
            float m = -1e30f;
#pragma unroll
            for (int j = 0; j < 32; j++) {
                x[j] = Sf[row * PS + j * 32 + lane] * 0.0625f;
                m = fmaxf(m, x[j]);
            }
#pragma unroll
            for (int o = 16; o; o >>= 1) m = fmaxf(m, __shfl_xor_sync(0xffffffffu, m, o));
#pragma unroll
            for (int j = 0; j < 32; j++) x[j] -= m;

            float tau = -1.0f;
#pragma unroll 1
            for (int it = 0; it < NEWTON; it++) {
                float s = 0.f, r = 0.f;
#pragma unroll
                for (int j = 0; j < 32; j++) {
                    float u = fmaxf(x[j] - tau, 0.f);
                    s = fmaf(u, u, s);
                    r += u;
                }
#pragma unroll
                for (int o = 16; o; o >>= 1) {
                    s += __shfl_xor_sync(0xffffffffu, s, o);
                    r += __shfl_xor_sync(0xffffffffu, r, o);
                }
                tau += (s - 1.0f) / (2.0f * r);
            }
#pragma unroll
            for (int j = 0; j < 32; j++) {
                float u = fmaxf(x[j] - tau, 0.f);
                Sw[row * PS + j * 32 + lane] = pack1(u * u);
            }
        }
    }

    // ======================= GEMM2: O = P V (16 tiles of 64 keys) ===========
    // warp wid owns d columns [wid*8, wid*8+8)
    const int vAdr = (wid * 8 + (lane & 7)) * 144 + ((lane >> 3) & 1) * 16;
    float oc[4] = {0.f, 0.f, 0.f, 0.f};

    for (int vt = 0; vt < 16; vt++) {
        const int buf = vt & 1;
        CP_WAIT0();
        __syncthreads();
        if (vt < 15) {
            const int nb = buf ^ 1;
#pragma unroll
            for (int i = 0; i < 2; i++) {
                int idx = i * NTHR + tid;
                int row = idx >> 3, seg = idx & 7;
                int gi = bh * 8192 + row * 128 + (vt + 1) * 8 + seg;
                cp16(smb + (KB_W + nb * 4608 + row * 36 + seg * 4) * 4, g_VTH + gi);
                cp16(smb + (KB_W + nb * 4608 + 2304 + row * 36 + seg * 4) * 4, g_VTL + gi);
            }
            CP_COMMIT();
        }
        const u32 VHB = smb + (KB_W + buf * 4608) * 4;
        const u32 VLB = VHB + 9216;

#pragma unroll
        for (int ksl = 0; ksl < 4; ksl++) {
            const int kw = vt * 64 + ksl * 16 + 2 * t;
            u32 ah[4], al[4];
            ldA(Sw + g * PS + kw, ah, al);
            u32 b2h[2], b2l[2];
            ldmx2(VHB + vAdr + ksl * 32, b2h);
            ldmx2(VLB + vAdr + ksl * 32, b2l);
            mma16816(oc, ah, b2h[0], b2h[1]);
            mma16816(oc, ah, b2l[0], b2l[1]);
            mma16816(oc, al, b2h[0], b2h[1]);
        }
    }

    // ---- write O directly (warp owns distinct d-slice; no reduction) ----
    {
        const int d = wid * 8 + 2 * t;
        *(float2*)&Og[g * DH + d]       = make_float2(oc[0], oc[1]);
        *(float2*)&Og[(g + 8) * DH + d] = make_float2(oc[2], oc[3]);
    }
}

extern "C" void kernel_launch(void* const* d_in, const int* in_sizes, int n_in,
                              void* d_out, int out_size)
{
    const float* q = (const float*)d_in[0];
    const float* k = (const float*)d_in[1];
    const float* v = (const float*)d_in[2];
    float* out = (float*)d_out;

    cudaFuncSetAttribute(attn_entmax15_p,
                         cudaFuncAttributeMaxDynamicSharedMemorySize, SMEM_BYTES);

    prepQK<<<2048, 512>>>((const float4*)q, (const float4*)k);
    prepV<<<dim3(64, 8), 256>>>(v);
    dim3 grid(SEQ / QT, 8 * 8);   // (64 q-tiles, 64 bh)
    attn_entmax15_p<<<grid, NTHR, SMEM_BYTES>>>(out);
}